// round 1
// baseline (speedup 1.0000x reference)
#include <cuda_runtime.h>
#include <math.h>

#define NANCH   8400
#define MAXB    32
#define NCLS    80
#define MAXDET  100
#define NBKT    1024
#define CHUNK   1024

// ---------------- device scratch (no allocations allowed) ----------------
__device__ float  g_scores[MAXB * NANCH];
__device__ float4 g_boxes [MAXB * NANCH];
__device__ int    g_labels[MAXB * NANCH];
__device__ int    g_maxabs[MAXB];   // float bits (non-negative) for atomicMax

// ---------------- init ----------------
__global__ void k_init() {
    if (threadIdx.x < MAXB) g_maxabs[threadIdx.x] = 0;
}

__device__ __forceinline__ float sigmoidf_(float x) {
    return 1.0f / (1.0f + expf(-x));
}

// ---------------- decode: per-anchor score/label/box + per-image max|coord| ----------------
__global__ void k_decode(const float* __restrict__ cls0, const float* __restrict__ reg0, const float* __restrict__ obj0,
                         const float* __restrict__ cls1, const float* __restrict__ reg1, const float* __restrict__ obj1,
                         const float* __restrict__ cls2, const float* __restrict__ reg2, const float* __restrict__ obj2)
{
    int b = blockIdx.y;
    int a = blockIdx.x * blockDim.x + threadIdx.x;
    float m4 = 0.0f;
    if (a < NANCH) {
        const float *cls, *reg, *obj;
        int a0, w, hw; float s;
        if (a < 6400)      { cls = cls0; reg = reg0; obj = obj0; a0 = a;        w = 80; hw = 6400; s = 8.0f;  }
        else if (a < 8000) { cls = cls1; reg = reg1; obj = obj1; a0 = a - 6400; w = 40; hw = 1600; s = 16.0f; }
        else               { cls = cls2; reg = reg2; obj = obj2; a0 = a - 8000; w = 20; hw = 400;  s = 32.0f; }

        const float* cb = cls + (size_t)b * NCLS * hw + a0;
        float m = cb[0];
        int lab = 0;
        #pragma unroll 8
        for (int c = 1; c < NCLS; ++c) {
            float v = cb[(size_t)c * hw];
            if (v > m) { m = v; lab = c; }     // strict > keeps first max (argmax semantics)
        }
        float ov = obj[(size_t)b * hw + a0];
        float score = __fmul_rn(sigmoidf_(m), sigmoidf_(ov));

        const float* rb = reg + (size_t)b * 4 * hw + a0;
        float r0 = rb[0], r1 = rb[hw], r2 = rb[2 * hw], r3 = rb[3 * hw];
        float px = (float)(a0 % w) * s;   // exact
        float py = (float)(a0 / w) * s;   // exact
        float cx = __fadd_rn(__fmul_rn(r0, s), px);
        float cy = __fadd_rn(__fmul_rn(r1, s), py);
        float bw = __fmul_rn(expf(r2), s);
        float bh = __fmul_rn(expf(r3), s);
        float hx = __fmul_rn(bw, 0.5f);
        float hy = __fmul_rn(bh, 0.5f);
        float x1 = __fsub_rn(cx, hx), y1 = __fsub_rn(cy, hy);
        float x2 = __fadd_rn(cx, hx), y2 = __fadd_rn(cy, hy);

        size_t gi = (size_t)b * NANCH + a;
        g_scores[gi] = score;
        g_labels[gi] = lab;
        g_boxes[gi]  = make_float4(x1, y1, x2, y2);
        m4 = fmaxf(fmaxf(fabsf(x1), fabsf(y1)), fmaxf(fabsf(x2), fabsf(y2)));
    }
    __shared__ float red[256];
    red[threadIdx.x] = m4;
    __syncthreads();
    #pragma unroll
    for (int off = 128; off > 0; off >>= 1) {
        if (threadIdx.x < off) red[threadIdx.x] = fmaxf(red[threadIdx.x], red[threadIdx.x + off]);
        __syncthreads();
    }
    if (threadIdx.x == 0)
        atomicMax(&g_maxabs[b], __float_as_int(red[0]));   // non-negative floats: int order == float order
}

// ---------------- NMS: histogram -> bucket chunk -> bitonic sort -> greedy scan ----------------
__global__ void __launch_bounds__(1024) k_nms(float* __restrict__ out, int B)
{
    __shared__ int                s_hist[NBKT];
    __shared__ unsigned long long s_chunk[CHUNK];
    __shared__ float4             s_topbox[CHUNK];
    __shared__ float4             s_keptb[MAXDET];
    __shared__ int                s_kepti[MAXDET];
    __shared__ int                s_cnt, s_kc, s_lo, s_hi, s_ptr;

    const int b   = blockIdx.x;
    const int tid = threadIdx.x;
    const size_t base = (size_t)b * NANCH;
    const float off = __int_as_float(g_maxabs[b]) + 1.0f;

    if (tid == 0) { s_ptr = NBKT - 1; s_kc = 0; }
    s_hist[tid] = 0;
    __syncthreads();

    // histogram of live candidates by linear score bucket
    for (int i = tid; i < NANCH; i += 1024) {
        float sc = g_scores[base + i];
        if (sc >= 0.01f) {
            int bkt = (int)(sc * 1024.0f);
            if (bkt > NBKT - 1) bkt = NBKT - 1;
            atomicAdd(&s_hist[bkt], 1);
        }
    }
    __syncthreads();

    for (;;) {
        __syncthreads();
        if (s_kc >= MAXDET || s_ptr < 0) break;

        // thread 0: walk buckets downward to form next chunk [s_lo, s_hi]
        if (tid == 0) {
            int acc = 0;
            int hi = s_ptr, p = hi;
            while (p >= 0) {
                int h = s_hist[p];
                if (acc > 0 && acc + h > CHUNK) break;
                acc += h; --p;
                if (acc >= 384) break;
            }
            s_lo = p + 1; s_hi = hi; s_ptr = p; s_cnt = 0;
        }
        __syncthreads();
        int lo = s_lo, hi = s_hi;

        // compact candidates in bucket range into shared chunk (key: score desc, idx asc)
        for (int i = tid; i < NANCH; i += 1024) {
            float sc = g_scores[base + i];
            if (sc >= 0.01f) {
                int bkt = (int)(sc * 1024.0f);
                if (bkt > NBKT - 1) bkt = NBKT - 1;
                if (bkt >= lo && bkt <= hi) {
                    int p = atomicAdd(&s_cnt, 1);
                    if (p < CHUNK) {
                        unsigned u = __float_as_uint(sc);
                        u = ~(u ^ 0x80000000u);   // positive-float descending key
                        s_chunk[p] = ((unsigned long long)u << 32) | (unsigned)i;
                    }
                }
            }
        }
        __syncthreads();
        int cN = s_cnt; if (cN > CHUNK) cN = CHUNK;
        if (tid >= cN) s_chunk[tid] = 0xFFFFFFFFFFFFFFFFull;   // pad sorts last
        __syncthreads();

        // bitonic sort CHUNK=1024 keys ascending (== score descending, idx ascending)
        for (int k = 2; k <= CHUNK; k <<= 1) {
            for (int j = k >> 1; j > 0; j >>= 1) {
                int i = tid, l = i ^ j;
                if (l > i) {
                    unsigned long long A = s_chunk[i], Bv = s_chunk[l];
                    bool up = ((i & k) == 0);
                    if ((A > Bv) == up) { s_chunk[i] = Bv; s_chunk[l] = A; }
                }
                __syncthreads();
            }
        }

        // gather class-offset boxes for this chunk
        if (tid < cN) {
            int idx = (int)(s_chunk[tid] & 0xFFFFFFFFull);
            float4 bx = g_boxes[base + idx];
            float lf = (float)g_labels[base + idx];
            float t = __fmul_rn(lf, off);
            bx.x = __fadd_rn(bx.x, t);
            bx.y = __fadd_rn(bx.y, t);
            bx.z = __fadd_rn(bx.z, t);
            bx.w = __fadd_rn(bx.w, t);
            s_topbox[tid] = bx;
        }
        __syncthreads();

        // single-warp greedy scan: keep candidate iff IoU <= thr vs all kept
        if (tid < 32) {
            int lane = tid;
            int kc = s_kc;
            for (int c = 0; c < cN && kc < MAXDET; ++c) {
                float4 cbx = s_topbox[c];
                float ca = __fmul_rn(__fsub_rn(cbx.z, cbx.x), __fsub_rn(cbx.w, cbx.y));
                bool sup = false;
                for (int j = lane; j < kc; j += 32) {
                    float4 kb = s_keptb[j];
                    float tlx = fmaxf(kb.x, cbx.x), tly = fmaxf(kb.y, cbx.y);
                    float brx = fminf(kb.z, cbx.z), bry = fminf(kb.w, cbx.w);
                    float ww = fmaxf(__fsub_rn(brx, tlx), 0.0f);
                    float hh = fmaxf(__fsub_rn(bry, tly), 0.0f);
                    float inter = __fmul_rn(ww, hh);
                    float a1 = __fmul_rn(__fsub_rn(kb.z, kb.x), __fsub_rn(kb.w, kb.y));
                    float den = __fadd_rn(__fsub_rn(__fadd_rn(a1, ca), inter), 1e-6f);
                    float iou = __fdiv_rn(inter, den);
                    if (iou > 0.65f) { sup = true; break; }
                }
                if (!__any_sync(0xFFFFFFFFu, sup)) {
                    if (lane == 0) {
                        s_keptb[kc] = cbx;
                        s_kepti[kc] = (int)(s_chunk[c] & 0xFFFFFFFFull);
                    }
                    ++kc;
                    __syncwarp();
                }
            }
            if (lane == 0) s_kc = kc;
        }
        // loop-top __syncthreads orders s_kc for everyone
    }
    __syncthreads();

    // ---------------- write outputs: boxes | scores | labels | valid ----------------
    int kc = s_kc;
    float* ob  = out;                              // [B,100,4]
    float* osc = out + (size_t)B * MAXDET * 4;     // [B,100]
    float* olb = osc + (size_t)B * MAXDET;         // [B,100]
    float* ovl = olb + (size_t)B * MAXDET;         // [B,100]

    if (tid < MAXDET) {
        int r = tid;
        float4 bx = make_float4(0.f, 0.f, 0.f, 0.f);
        float sc = 0.f, lb = -1.f, vl = 0.f;
        if (r < kc) {
            int idx = s_kepti[r];
            bx = g_boxes[base + idx];
            sc = g_scores[base + idx];
            lb = (float)g_labels[base + idx];
            vl = 1.0f;
        }
        float* obp = ob + ((size_t)b * MAXDET + r) * 4;
        obp[0] = bx.x; obp[1] = bx.y; obp[2] = bx.z; obp[3] = bx.w;
        osc[(size_t)b * MAXDET + r] = sc;
        olb[(size_t)b * MAXDET + r] = lb;
        ovl[(size_t)b * MAXDET + r] = vl;
    }
}

// ---------------- launch ----------------
extern "C" void kernel_launch(void* const* d_in, const int* in_sizes, int n_in,
                              void* d_out, int out_size)
{
    // cls0 size = B*80*6400 = B*512000 in either ordering
    int B = in_sizes[0] / 512000;
    if (B < 1) B = 1;
    if (B > MAXB) B = MAXB;

    const float *cls[3], *reg[3], *obj[3];
    // grouped order: cls0,cls1,cls2,reg0,reg1,reg2,obj0,obj1,obj2 -> in_sizes[1] = B*80*1600
    // interleaved  : cls0,reg0,obj0,cls1,reg1,obj1,cls2,reg2,obj2 -> in_sizes[1] = B*4*6400
    bool grouped = (n_in >= 9) && (in_sizes[1] == B * 128000);
    if (grouped) {
        for (int i = 0; i < 3; ++i) {
            cls[i] = (const float*)d_in[i];
            reg[i] = (const float*)d_in[3 + i];
            obj[i] = (const float*)d_in[6 + i];
        }
    } else {
        for (int i = 0; i < 3; ++i) {
            cls[i] = (const float*)d_in[3 * i];
            reg[i] = (const float*)d_in[3 * i + 1];
            obj[i] = (const float*)d_in[3 * i + 2];
        }
    }

    k_init<<<1, 32>>>();
    dim3 g1((NANCH + 255) / 256, B);
    k_decode<<<g1, 256>>>(cls[0], reg[0], obj[0],
                          cls[1], reg[1], obj[1],
                          cls[2], reg[2], obj[2]);
    k_nms<<<B, 1024>>>((float*)d_out, B);
}